// round 14
// baseline (speedup 1.0000x reference)
#include <cuda_runtime.h>
#include <cuda_fp16.h>
#include <cstdint>

// ---------------------------------------------------------------- constants
#define EPSV 0.007f
#define NPIX 25088              // 32*28*28 = 196 * 128
#define KA   1152
#define KB   2432               // 9*256 + 128 shortcut
#define NKA  36
#define NKB  76

#define ROWB      80            // padded bytes per 32-fp16 k-row
#define OFF_B     10240         // A: 128 rows * 80B, then B: 128 rows * 80B
#define STAGE_SZ  20480
#define NSTG      4
#define DYN_SMEM  81920         // 4*STAGE_SZ; >= epilogue 128*132*4=67584

// ---------------------------------------------------------------- globals
__device__ __align__(256) __half g_xhi[(size_t)32 * 56 * 56 * 128];
__device__ __align__(256) __half g_yhi[(size_t)NPIX * 256];
__device__ __align__(256) float g_xs2[32 * 56 * 56];
__device__ __align__(256) float g_psq[NPIX];
__device__ __align__(256) __half g_wA[256 * KA];
__device__ __align__(256) __half g_wB[256 * KB];
__device__ __align__(256) float g_wsq[256];

// ---------------------------------------------------------------- ptx utils
__device__ __forceinline__ uint32_t smem_u32(const void* p) {
    return (uint32_t)__cvta_generic_to_shared(p);
}
__device__ __forceinline__ void cpa16(uint32_t dst, const void* src, uint32_t sz) {
    asm volatile("cp.async.cg.shared.global [%0], [%1], 16, %2;"
                 :: "r"(dst), "l"(src), "r"(sz) : "memory");
}
#define CP_COMMIT() asm volatile("cp.async.commit_group;" ::: "memory")
#define CP_WAIT2()  asm volatile("cp.async.wait_group 2;" ::: "memory")

#define LDSM4(r0, r1, r2, r3, addr) \
    asm volatile("ldmatrix.sync.aligned.m8n8.x4.shared.b16 {%0,%1,%2,%3}, [%4];" \
                 : "=r"(r0), "=r"(r1), "=r"(r2), "=r"(r3) : "r"(addr))

#define MMAF16(C, A, B0, B1) \
    asm volatile("mma.sync.aligned.m16n8k16.row.col.f32.f16.f16.f32 " \
                 "{%0,%1,%2,%3}, {%4,%5,%6,%7}, {%8,%9}, {%0,%1,%2,%3};" \
                 : "+f"((C)[0]), "+f"((C)[1]), "+f"((C)[2]), "+f"((C)[3]) \
                 : "r"((A)[0]), "r"((A)[1]), "r"((A)[2]), "r"((A)[3]), \
                   "r"(B0), "r"(B1))

// ---------------------------------------------------------------- prep
__global__ __launch_bounds__(256) void prep_x(const float* __restrict__ x) {
    __shared__ float s[128][57];
    __shared__ float s2p[56][4];
    const int h = blockIdx.x, n = blockIdx.y;
    const float* xb = x + ((size_t)n * 128 * 56 + h) * 56;
    for (int idx = threadIdx.x; idx < 128 * 56; idx += 256) {
        int ci = idx / 56, wi = idx - 56 * ci;
        s[ci][wi] = xb[(size_t)ci * 3136 + wi];
    }
    __syncthreads();
    for (int idx = threadIdx.x; idx < 56 * 128; idx += 256) {
        int wi = idx >> 7, ci = idx & 127;
        g_xhi[((size_t)(n * 56 + h) * 56 + wi) * 128 + ci] = __float2half(s[ci][wi]);
    }
    if (threadIdx.x < 224) {
        int wi = threadIdx.x >> 2, q = threadIdx.x & 3;
        float a = 0.f;
        for (int ci = q * 32; ci < q * 32 + 32; ci++) { float v = s[ci][wi]; a += v * v; }
        s2p[wi][q] = a;
    }
    __syncthreads();
    if (threadIdx.x < 56) {
        int wi = threadIdx.x;
        g_xs2[(n * 56 + h) * 56 + wi] = s2p[wi][0] + s2p[wi][1] + s2p[wi][2] + s2p[wi][3];
    }
}

__global__ void prep_psq() {
    const int pw = threadIdx.x, ph = blockIdx.x, n = blockIdx.y;
    float s = 0.f;
    for (int dr = -1; dr <= 1; dr++) {
        int r = 2 * ph + dr;
        if ((unsigned)r >= 56) continue;
        for (int dc = -1; dc <= 1; dc++) {
            int c = 2 * pw + dc;
            if ((unsigned)c >= 56) continue;
            s += g_xs2[(n * 56 + r) * 56 + c];
        }
    }
    g_psq[(n * 28 + ph) * 28 + pw] = s;
}

// fused weight prep: blocks 0..255 -> w_yat (+wsq); 256..511 -> w_lin+w_short
__global__ __launch_bounds__(256) void prep_w(const float* __restrict__ wy,
                                              const float* __restrict__ wl,
                                              const float* __restrict__ ws) {
    __shared__ float red[256];
    if (blockIdx.x < 256) {
        const int co = blockIdx.x;
        float acc = 0.f;
        for (int k = threadIdx.x; k < KA; k += 256) {
            int kh = k / 384, rem = k - kh * 384, kw = rem >> 7, ci = rem & 127;
            float v = wy[(size_t)co * KA + ci * 9 + kh * 3 + kw];
            g_wA[(size_t)co * KA + k] = __float2half(v);
            acc += v * v;
        }
        red[threadIdx.x] = acc;
        __syncthreads();
        for (int o = 128; o > 0; o >>= 1) {
            if (threadIdx.x < o) red[threadIdx.x] += red[threadIdx.x + o];
            __syncthreads();
        }
        if (threadIdx.x == 0) g_wsq[co] = red[0];
    } else {
        const int co = blockIdx.x - 256;
        for (int k = threadIdx.x; k < 2304; k += 256) {
            int kh = k / 768, rem = k - kh * 768, kw = rem >> 8, ci = rem & 255;
            g_wB[(size_t)co * KB + k] =
                __float2half(wl[(size_t)co * 2304 + ci * 9 + kh * 3 + kw]);
        }
        for (int k = threadIdx.x; k < 128; k += 256)
            g_wB[(size_t)co * KB + 2304 + k] = __float2half(ws[co * 128 + k]);
    }
}

// ---------------------------------------------------------------- k-block fill
// stage buffer: [A 10240][B 10240]; 128 rows x 32 fp16, rows padded to 80B
__device__ __forceinline__ void fill_tile(int stage, int kb, uint32_t sbuf,
                                          int t, int ctaM, int ctaN) {
#pragma unroll
    for (int j = 0; j < 4; j++) {
        const int idx = t + 256 * j;
        const int ch = idx & 3;
        if (idx < 512) {
            const int row = idx >> 2;
            const int p   = ctaM * 128 + row;
            const int n   = p / 784;
            const int rem = p - n * 784;
            const int ph  = rem / 28;
            const int pw  = rem - ph * 28;
            const __half* src;
            uint32_t ok;
            if (stage == 0) {
                int tap = kb >> 2, kh = tap / 3, kw = tap - 3 * (tap / 3);
                int ci0 = (kb & 3) * 32;
                int r = 2 * ph - 1 + kh, c = 2 * pw - 1 + kw;
                bool v = ((unsigned)r < 56) && ((unsigned)c < 56);
                size_t off = v ? ((size_t)((n * 56 + r) * 56 + c) * 128 + ci0) : 0;
                src = g_xhi + off; ok = v ? 16u : 0u;
            } else if (kb < 72) {
                int tap = kb >> 3, kh = tap / 3, kw = tap - 3 * (tap / 3);
                int co0 = (kb & 7) * 32;
                int r = ph - 1 + kh, c = pw - 1 + kw;
                bool v = ((unsigned)r < 28) && ((unsigned)c < 28);
                size_t off = v ? ((size_t)((n * 28 + r) * 28 + c) * 256 + co0) : 0;
                src = g_yhi + off; ok = v ? 16u : 0u;
            } else {
                int ci0 = (kb - 72) * 32;
                size_t off = (size_t)((n * 56 + 2 * ph) * 56 + 2 * pw) * 128 + ci0;
                src = g_xhi + off; ok = 16u;
            }
            cpa16(sbuf + row * ROWB + ch * 16, (const char*)src + ch * 16, ok);
        } else {
            const int widx = idx - 512;          // 0..511
            const int row  = widx >> 2;          // 0..127
            const int co   = ctaN * 128 + row;
            const __half* src = stage ? (g_wB + (size_t)co * KB + kb * 32)
                                      : (g_wA + (size_t)co * KA + kb * 32);
            cpa16(sbuf + OFF_B + row * ROWB + ch * 16,
                  (const char*)src + ch * 16, 16u);
        }
    }
}

// ---------------------------------------------------------------- GEMM kernel
// CTA 128 px x 128 co; 8 warps 4(m) x 2(n); warp tile 32 x 64.
// fp16 single pass, fp32 accum. 4-stage cp.async pipeline (+3 prefetch).
// Inner loop: B-fragment double buffer — LDSM of ip16+1 issued before MMAs
// of ip16, hiding LDS latency under tensor work.
__global__ __launch_bounds__(256, 2)
void gemm_kernel(int stage, const float* __restrict__ alpha, float* __restrict__ out) {
    extern __shared__ __align__(1024) char dsm[];
    __shared__ float s_psq[128];
    __shared__ float s_wsq[128];

    const int t    = threadIdx.x;
    const int lane = t & 31;
    const int w    = t >> 5;
    const int wm   = w & 3;
    const int wn   = w >> 2;
    const int ctaM = blockIdx.x;
    const int ctaN = blockIdx.y;
    const uint32_t sdyn = smem_u32(dsm);

    if (stage == 0 && t < 128) {
        s_psq[t] = g_psq[ctaM * 128 + t];
        s_wsq[t] = g_wsq[ctaN * 128 + t];
    }

    float acc[2][8][4];
#pragma unroll
    for (int a = 0; a < 2; a++)
#pragma unroll
        for (int b = 0; b < 8; b++)
#pragma unroll
            for (int c = 0; c < 4; c++) acc[a][b][c] = 0.f;

    const uint32_t aOff = (uint32_t)(wm * 32 + (lane & 15)) * ROWB + (lane >> 4) * 16;
    const uint32_t bOff = (uint32_t)(wn * 64 + (lane & 7) + ((lane >> 4) << 3)) * ROWB
                        + ((lane >> 3) & 1) * 16;

    const int NK = stage ? NKB : NKA;

    // prologue: 3 k-blocks in flight
    fill_tile(stage, 0, sdyn, t, ctaM, ctaN);                CP_COMMIT();
    fill_tile(stage, 1, sdyn + STAGE_SZ, t, ctaM, ctaN);     CP_COMMIT();
    fill_tile(stage, 2, sdyn + 2 * STAGE_SZ, t, ctaM, ctaN); CP_COMMIT();

    int buf = 0;
    for (int kb = 0; kb < NK; kb++) {
        CP_WAIT2();                 // group kb retired (<=2 younger pending)
        __syncthreads();            // buffer kb visible; compute(kb-1) done

        if (kb + 3 < NK) {
            int nb = buf + 3; if (nb >= NSTG) nb -= NSTG;
            fill_tile(stage, kb + 3, sdyn + nb * STAGE_SZ, t, ctaM, ctaN);
        }
        CP_COMMIT();                // one group per iteration (may be empty)

        const uint32_t sb = sdyn + buf * STAGE_SZ;
#pragma unroll
        for (int kc = 0; kc < 2; kc++) {
            const uint32_t kByte = kc * 32;
            uint32_t ah[2][4];
            LDSM4(ah[0][0], ah[0][1], ah[0][2], ah[0][3], sb + aOff + kByte);
            LDSM4(ah[1][0], ah[1][1], ah[1][2], ah[1][3],
                  sb + aOff + 16 * ROWB + kByte);

            const uint32_t bbase = sb + OFF_B + bOff + kByte;
            uint32_t bfr[2][4];
            LDSM4(bfr[0][0], bfr[0][1], bfr[0][2], bfr[0][3], bbase);
#pragma unroll
            for (int ip16 = 0; ip16 < 4; ip16++) {
                if (ip16 < 3) {
                    uint32_t* nb_ = bfr[(ip16 + 1) & 1];
                    LDSM4(nb_[0], nb_[1], nb_[2], nb_[3],
                          bbase + (ip16 + 1) * (16 * ROWB));
                }
                const uint32_t* b = bfr[ip16 & 1];
                MMAF16(acc[0][2 * ip16],     ah[0], b[0], b[1]);
                MMAF16(acc[1][2 * ip16],     ah[1], b[0], b[1]);
                MMAF16(acc[0][2 * ip16 + 1], ah[0], b[2], b[3]);
                MMAF16(acc[1][2 * ip16 + 1], ah[1], b[2], b[3]);
            }
        }
        if (++buf == NSTG) buf = 0;
    }
    __syncthreads();

    // ---------------- epilogue ----------------
    if (stage == 0) {
        const float scale = powf(16.0f / logf(257.0f), alpha[0]);
#pragma unroll
        for (int im = 0; im < 2; im++) {
#pragma unroll
            for (int ip8 = 0; ip8 < 8; ip8++) {
                const int cl = wn * 64 + ip8 * 8 + 2 * (lane & 3);
                const float wq0 = s_wsq[cl], wq1 = s_wsq[cl + 1];
                const float* c = acc[im][ip8];
#pragma unroll
                for (int s = 0; s < 2; s++) {
                    const int pl = wm * 32 + im * 16 + (lane >> 2) + 8 * s;
                    const int p  = ctaM * 128 + pl;
                    const float psqv = s_psq[pl];
                    const float f0 = c[2 * s], f1 = c[2 * s + 1];
                    const float y0 = scale * f0 * f0 / (psqv + wq0 - 2.f * f0 + EPSV);
                    const float y1 = scale * f1 * f1 / (psqv + wq1 - 2.f * f1 + EPSV);
                    const size_t oi = (size_t)p * 128 + ((ctaN * 128 + cl) >> 1);
                    ((uint32_t*)g_yhi)[oi] =
                        (uint32_t)__half_as_ushort(__float2half(y0)) |
                        ((uint32_t)__half_as_ushort(__float2half(y1)) << 16);
                }
            }
        }
    } else {
        float* sy = (float*)dsm;
#pragma unroll
        for (int im = 0; im < 2; im++) {
#pragma unroll
            for (int ip8 = 0; ip8 < 8; ip8++) {
                const int cl = wn * 64 + ip8 * 8 + 2 * (lane & 3);
                const float* c = acc[im][ip8];
#pragma unroll
                for (int s = 0; s < 2; s++) {
                    const int pl = wm * 32 + im * 16 + (lane >> 2) + 8 * s;
                    sy[cl * 132 + pl]       = c[2 * s];
                    sy[(cl + 1) * 132 + pl] = c[2 * s + 1];
                }
            }
        }
        __syncthreads();
        for (int i = t; i < 128 * 128; i += 256) {
            const int col = i >> 7, q = i & 127;
            const int p = ctaM * 128 + q;
            const int n = p / 784, rem = p - n * 784;
            out[(size_t)n * 200704 + (size_t)(ctaN * 128 + col) * 784 + rem] =
                sy[col * 132 + q];
        }
    }
}

// ---------------------------------------------------------------- launch
extern "C" void kernel_launch(void* const* d_in, const int* in_sizes, int n_in,
                              void* d_out, int out_size) {
    const float* x       = (const float*)d_in[0];
    const float* w_yat   = (const float*)d_in[1];
    const float* alpha   = (const float*)d_in[2];
    const float* w_lin   = (const float*)d_in[3];
    const float* w_short = (const float*)d_in[4];
    float* out = (float*)d_out;

    cudaFuncSetAttribute(gemm_kernel, cudaFuncAttributeMaxDynamicSharedMemorySize, DYN_SMEM);

    // order keeps ncu capture slot on gemm0
    prep_x  <<<dim3(56, 32), 256>>>(x);
    prep_w  <<<512, 256>>>(w_yat, w_lin, w_short);
    prep_psq<<<dim3(28, 32), 28>>>();

    dim3 grid(196, 2);
    gemm_kernel<<<grid, 256, DYN_SMEM>>>(0, alpha, out);   // YAT -> g_yhi
    gemm_kernel<<<grid, 256, DYN_SMEM>>>(1, alpha, out);   // lin + shortcut -> out
}

// round 15
// speedup vs baseline: 1.0354x; 1.0354x over previous
#include <cuda_runtime.h>
#include <cuda_fp16.h>
#include <cstdint>

// ---------------------------------------------------------------- constants
#define EPSV 0.007f
#define NPIX 25088              // 32*28*28 = 196 * 128
#define KA   1152
#define KB   2432               // 9*256 + 128 shortcut
#define NKA  36
#define NKB  76

#define ROWB      80            // padded bytes per 32-fp16 k-row
#define OFF_B     10240         // A: 128 rows * 80B, then B: 128 rows * 80B
#define STAGE_SZ  20480
#define NSTG      4
#define DYN_SMEM  81920         // 4*STAGE_SZ; >= epilogue 128*132*4=67584
#define NEGSENT   (-(1 << 28))  // invalid-offset sentinel

// ---------------------------------------------------------------- globals
__device__ __align__(256) __half g_xhi[(size_t)32 * 56 * 56 * 128];
__device__ __align__(256) __half g_yhi[(size_t)NPIX * 256];
__device__ __align__(256) float g_xs2[32 * 56 * 56];
__device__ __align__(256) float g_psq[NPIX];
__device__ __align__(256) __half g_wA[256 * KA];
__device__ __align__(256) __half g_wB[256 * KB];
__device__ __align__(256) float g_wsq[256];

// ---------------------------------------------------------------- ptx utils
__device__ __forceinline__ uint32_t smem_u32(const void* p) {
    return (uint32_t)__cvta_generic_to_shared(p);
}
__device__ __forceinline__ void cpa16(uint32_t dst, const void* src, uint32_t sz) {
    asm volatile("cp.async.cg.shared.global [%0], [%1], 16, %2;"
                 :: "r"(dst), "l"(src), "r"(sz) : "memory");
}
#define CP_COMMIT() asm volatile("cp.async.commit_group;" ::: "memory")
#define CP_WAIT2()  asm volatile("cp.async.wait_group 2;" ::: "memory")

#define LDSM4(r0, r1, r2, r3, addr) \
    asm volatile("ldmatrix.sync.aligned.m8n8.x4.shared.b16 {%0,%1,%2,%3}, [%4];" \
                 : "=r"(r0), "=r"(r1), "=r"(r2), "=r"(r3) : "r"(addr))

#define MMAF16(C, A, B0, B1) \
    asm volatile("mma.sync.aligned.m16n8k16.row.col.f32.f16.f16.f32 " \
                 "{%0,%1,%2,%3}, {%4,%5,%6,%7}, {%8,%9}, {%0,%1,%2,%3};" \
                 : "+f"((C)[0]), "+f"((C)[1]), "+f"((C)[2]), "+f"((C)[3]) \
                 : "r"((A)[0]), "r"((A)[1]), "r"((A)[2]), "r"((A)[3]), \
                   "r"(B0), "r"(B1))

// ---------------------------------------------------------------- prep
__global__ __launch_bounds__(256) void prep_x(const float* __restrict__ x) {
    __shared__ float s[128][57];
    __shared__ float s2p[56][4];
    const int h = blockIdx.x, n = blockIdx.y;
    const float* xb = x + ((size_t)n * 128 * 56 + h) * 56;
    for (int idx = threadIdx.x; idx < 128 * 56; idx += 256) {
        int ci = idx / 56, wi = idx - 56 * ci;
        s[ci][wi] = xb[(size_t)ci * 3136 + wi];
    }
    __syncthreads();
    for (int idx = threadIdx.x; idx < 56 * 128; idx += 256) {
        int wi = idx >> 7, ci = idx & 127;
        g_xhi[((size_t)(n * 56 + h) * 56 + wi) * 128 + ci] = __float2half(s[ci][wi]);
    }
    if (threadIdx.x < 224) {
        int wi = threadIdx.x >> 2, q = threadIdx.x & 3;
        float a = 0.f;
        for (int ci = q * 32; ci < q * 32 + 32; ci++) { float v = s[ci][wi]; a += v * v; }
        s2p[wi][q] = a;
    }
    __syncthreads();
    if (threadIdx.x < 56) {
        int wi = threadIdx.x;
        g_xs2[(n * 56 + h) * 56 + wi] = s2p[wi][0] + s2p[wi][1] + s2p[wi][2] + s2p[wi][3];
    }
}

__global__ void prep_psq() {
    const int pw = threadIdx.x, ph = blockIdx.x, n = blockIdx.y;
    float s = 0.f;
    for (int dr = -1; dr <= 1; dr++) {
        int r = 2 * ph + dr;
        if ((unsigned)r >= 56) continue;
        for (int dc = -1; dc <= 1; dc++) {
            int c = 2 * pw + dc;
            if ((unsigned)c >= 56) continue;
            s += g_xs2[(n * 56 + r) * 56 + c];
        }
    }
    g_psq[(n * 28 + ph) * 28 + pw] = s;
}

// fused weight prep: blocks 0..255 -> w_yat (+wsq); 256..511 -> w_lin+w_short
__global__ __launch_bounds__(256) void prep_w(const float* __restrict__ wy,
                                              const float* __restrict__ wl,
                                              const float* __restrict__ ws) {
    __shared__ float red[256];
    if (blockIdx.x < 256) {
        const int co = blockIdx.x;
        float acc = 0.f;
        for (int k = threadIdx.x; k < KA; k += 256) {
            int kh = k / 384, rem = k - kh * 384, kw = rem >> 7, ci = rem & 127;
            float v = wy[(size_t)co * KA + ci * 9 + kh * 3 + kw];
            g_wA[(size_t)co * KA + k] = __float2half(v);
            acc += v * v;
        }
        red[threadIdx.x] = acc;
        __syncthreads();
        for (int o = 128; o > 0; o >>= 1) {
            if (threadIdx.x < o) red[threadIdx.x] += red[threadIdx.x + o];
            __syncthreads();
        }
        if (threadIdx.x == 0) g_wsq[co] = red[0];
    } else {
        const int co = blockIdx.x - 256;
        for (int k = threadIdx.x; k < 2304; k += 256) {
            int kh = k / 768, rem = k - kh * 768, kw = rem >> 8, ci = rem & 255;
            g_wB[(size_t)co * KB + k] =
                __float2half(wl[(size_t)co * 2304 + ci * 9 + kh * 3 + kw]);
        }
        for (int k = threadIdx.x; k < 128; k += 256)
            g_wB[(size_t)co * KB + 2304 + k] = __float2half(ws[co * 128 + k]);
    }
}

// ---------------------------------------------------------------- GEMM kernel
// CTA 128 px x 128 co; 8 warps 4(m) x 2(n); warp tile 32 x 64.
// fp16 single pass, fp32 accum. 4-stage cp.async pipeline (+3 prefetch).
// All per-pixel address math hoisted out of the k-loop into sign-coded
// offset tables; per-k-block fill is ~25 instructions.
__global__ __launch_bounds__(256, 2)
void gemm_kernel(int stage, const float* __restrict__ alpha, float* __restrict__ out) {
    extern __shared__ __align__(1024) char dsm[];
    __shared__ float s_psq[128];
    __shared__ float s_wsq[128];

    const int t    = threadIdx.x;
    const int lane = t & 31;
    const int w    = t >> 5;
    const int wm   = w & 3;
    const int wn   = w >> 2;
    const int ctaM = blockIdx.x;
    const int ctaN = blockIdx.y;
    const uint32_t sdyn = smem_u32(dsm);

    if (stage == 0 && t < 128) {
        s_psq[t] = g_psq[ctaM * 128 + t];
        s_wsq[t] = g_wsq[ctaN * 128 + t];
    }

    // ---------- hoisted per-thread fill descriptors ----------
    const int ch   = t & 3;                 // 16B chunk within 64B row
    const int row0 = t >> 2;                // A/B row pair: row0, row0+64
    // smem destinations (fixed per thread, relative to stage buffer)
    const uint32_t dA0 = (uint32_t)row0 * ROWB + ch * 16;
    const uint32_t dA1 = dA0 + 64 * ROWB;
    const uint32_t dB0 = OFF_B + dA0;
    const uint32_t dB1 = OFF_B + dA1;
    // offset tables: R*[kh] row-base (elements), C*[kw] col offset; NEGSENT = OOB
    int R0a, R1a, R2a, C0a, C1a, C2a, Sa;
    int R0b, R1b, R2b, C0b, C1b, C2b, Sb;
#pragma unroll
    for (int i = 0; i < 2; i++) {
        const int p   = ctaM * 128 + row0 + 64 * i;
        const int n   = p / 784;
        const int rem = p - n * 784;
        const int ph  = rem / 28;
        const int pw  = rem - ph * 28;
        int R[3], C[3], S;
        if (stage == 0) {
#pragma unroll
            for (int kh = 0; kh < 3; kh++) {
                int r = 2 * ph - 1 + kh;
                R[kh] = ((unsigned)r < 56) ? (n * 56 + r) * 7168 : NEGSENT;
            }
#pragma unroll
            for (int kw = 0; kw < 3; kw++) {
                int c = 2 * pw - 1 + kw;
                C[kw] = ((unsigned)c < 56) ? c * 128 : NEGSENT;
            }
            S = 0;
        } else {
#pragma unroll
            for (int kh = 0; kh < 3; kh++) {
                int r = ph - 1 + kh;
                R[kh] = ((unsigned)r < 28) ? (n * 28 + r) * 7168 : NEGSENT;
            }
#pragma unroll
            for (int kw = 0; kw < 3; kw++) {
                int c = pw - 1 + kw;
                C[kw] = ((unsigned)c < 28) ? c * 256 : NEGSENT;
            }
            S = ((n * 56 + 2 * ph) * 56 + 2 * pw) * 128;   // shortcut rows (g_xhi)
        }
        if (i == 0) { R0a = R[0]; R1a = R[1]; R2a = R[2];
                      C0a = C[0]; C1a = C[1]; C2a = C[2]; Sa = S; }
        else        { R0b = R[0]; R1b = R[1]; R2b = R[2];
                      C0b = C[0]; C1b = C[1]; C2b = C[2]; Sb = S; }
    }
    const __half* const aBaseMain = stage ? g_yhi : g_xhi;   // main-tap A source
    const __half* bp0, *bp1;                                 // B row pointers
    if (stage) { bp0 = g_wB + (size_t)(ctaN * 128 + row0) * KB;
                 bp1 = g_wB + (size_t)(ctaN * 128 + row0 + 64) * KB; }
    else       { bp0 = g_wA + (size_t)(ctaN * 128 + row0) * KA;
                 bp1 = g_wA + (size_t)(ctaN * 128 + row0 + 64) * KA; }
    const int chB = ch * 16;

    float acc[2][8][4];
#pragma unroll
    for (int a = 0; a < 2; a++)
#pragma unroll
        for (int b = 0; b < 8; b++)
#pragma unroll
            for (int c = 0; c < 4; c++) acc[a][b][c] = 0.f;

    const uint32_t aOff = (uint32_t)(wm * 32 + (lane & 15)) * ROWB + (lane >> 4) * 16;
    const uint32_t bOff = (uint32_t)(wn * 64 + (lane & 7) + ((lane >> 4) << 3)) * ROWB
                        + ((lane >> 3) & 1) * 16;

    const int NK = stage ? NKB : NKA;

    // ---------- lightweight per-k-block fill ----------
    auto fill_kb = [&](int kb, uint32_t sbuf) {
        int offA0, offA1;
        if (stage == 0) {
            int tap = kb >> 2, ci0 = (kb & 3) << 5;
            int kh = (tap * 11) >> 5, kw = tap - 3 * kh;
            int rv0 = (kh == 0) ? R0a : (kh == 1) ? R1a : R2a;
            int cv0 = (kw == 0) ? C0a : (kw == 1) ? C1a : C2a;
            int rv1 = (kh == 0) ? R0b : (kh == 1) ? R1b : R2b;
            int cv1 = (kw == 0) ? C0b : (kw == 1) ? C1b : C2b;
            offA0 = rv0 + cv0 + ci0;
            offA1 = rv1 + cv1 + ci0;
        } else if (kb < 72) {
            int tap = kb >> 3, ci0 = (kb & 7) << 5;
            int kh = (tap * 11) >> 5, kw = tap - 3 * kh;
            int rv0 = (kh == 0) ? R0a : (kh == 1) ? R1a : R2a;
            int cv0 = (kw == 0) ? C0a : (kw == 1) ? C1a : C2a;
            int rv1 = (kh == 0) ? R0b : (kh == 1) ? R1b : R2b;
            int cv1 = (kw == 0) ? C0b : (kw == 1) ? C1b : C2b;
            offA0 = rv0 + cv0 + ci0;
            offA1 = rv1 + cv1 + ci0;
        } else {
            int ci0 = (kb - 72) << 5;
            offA0 = Sa + ci0;
            offA1 = Sb + ci0;
        }
        const __half* aBase = (stage && kb >= 72) ? g_xhi : aBaseMain;
        uint32_t ok0 = (offA0 >= 0) ? 16u : 0u;
        uint32_t ok1 = (offA1 >= 0) ? 16u : 0u;
        offA0 = max(offA0, 0);
        offA1 = max(offA1, 0);
        cpa16(sbuf + dA0, (const char*)(aBase + offA0) + chB, ok0);
        cpa16(sbuf + dA1, (const char*)(aBase + offA1) + chB, ok1);
        cpa16(sbuf + dB0, (const char*)(bp0 + kb * 32) + chB, 16u);
        cpa16(sbuf + dB1, (const char*)(bp1 + kb * 32) + chB, 16u);
    };

    // prologue: 3 k-blocks in flight
    fill_kb(0, sdyn);                 CP_COMMIT();
    fill_kb(1, sdyn + STAGE_SZ);      CP_COMMIT();
    fill_kb(2, sdyn + 2 * STAGE_SZ);  CP_COMMIT();

    int buf = 0;
    for (int kb = 0; kb < NK; kb++) {
        CP_WAIT2();                 // group kb retired (<=2 younger pending)
        __syncthreads();            // buffer kb visible; compute(kb-1) done

        if (kb + 3 < NK) {
            int nb = buf + 3; if (nb >= NSTG) nb -= NSTG;
            fill_kb(kb + 3, sdyn + nb * STAGE_SZ);
        }
        CP_COMMIT();                // one group per iteration (may be empty)

        const uint32_t sb = sdyn + buf * STAGE_SZ;
#pragma unroll
        for (int kc = 0; kc < 2; kc++) {
            const uint32_t kByte = kc * 32;
            uint32_t ah[2][4];
            LDSM4(ah[0][0], ah[0][1], ah[0][2], ah[0][3], sb + aOff + kByte);
            LDSM4(ah[1][0], ah[1][1], ah[1][2], ah[1][3],
                  sb + aOff + 16 * ROWB + kByte);
#pragma unroll
            for (int ip16 = 0; ip16 < 4; ip16++) {
                uint32_t baddr = sb + OFF_B + bOff + ip16 * (16 * ROWB) + kByte;
                uint32_t b0, b1, b2, b3;
                LDSM4(b0, b1, b2, b3, baddr);
                MMAF16(acc[0][2 * ip16],     ah[0], b0, b1);
                MMAF16(acc[1][2 * ip16],     ah[1], b0, b1);
                MMAF16(acc[0][2 * ip16 + 1], ah[0], b2, b3);
                MMAF16(acc[1][2 * ip16 + 1], ah[1], b2, b3);
            }
        }
        if (++buf == NSTG) buf = 0;
    }
    __syncthreads();

    // ---------------- epilogue ----------------
    if (stage == 0) {
        const float scale = powf(16.0f / logf(257.0f), alpha[0]);
#pragma unroll
        for (int im = 0; im < 2; im++) {
#pragma unroll
            for (int ip8 = 0; ip8 < 8; ip8++) {
                const int cl = wn * 64 + ip8 * 8 + 2 * (lane & 3);
                const float wq0 = s_wsq[cl], wq1 = s_wsq[cl + 1];
                const float* c = acc[im][ip8];
#pragma unroll
                for (int s = 0; s < 2; s++) {
                    const int pl = wm * 32 + im * 16 + (lane >> 2) + 8 * s;
                    const int p  = ctaM * 128 + pl;
                    const float psqv = s_psq[pl];
                    const float f0 = c[2 * s], f1 = c[2 * s + 1];
                    const float y0 = scale * f0 * f0 / (psqv + wq0 - 2.f * f0 + EPSV);
                    const float y1 = scale * f1 * f1 / (psqv + wq1 - 2.f * f1 + EPSV);
                    const size_t oi = (size_t)p * 128 + ((ctaN * 128 + cl) >> 1);
                    ((uint32_t*)g_yhi)[oi] =
                        (uint32_t)__half_as_ushort(__float2half(y0)) |
                        ((uint32_t)__half_as_ushort(__float2half(y1)) << 16);
                }
            }
        }
    } else {
        float* sy = (float*)dsm;
#pragma unroll
        for (int im = 0; im < 2; im++) {
#pragma unroll
            for (int ip8 = 0; ip8 < 8; ip8++) {
                const int cl = wn * 64 + ip8 * 8 + 2 * (lane & 3);
                const float* c = acc[im][ip8];
#pragma unroll
                for (int s = 0; s < 2; s++) {
                    const int pl = wm * 32 + im * 16 + (lane >> 2) + 8 * s;
                    sy[cl * 132 + pl]       = c[2 * s];
                    sy[(cl + 1) * 132 + pl] = c[2 * s + 1];
                }
            }
        }
        __syncthreads();
        for (int i = t; i < 128 * 128; i += 256) {
            const int col = i >> 7, q = i & 127;
            const int p = ctaM * 128 + q;
            const int n = p / 784, rem = p - n * 784;
            out[(size_t)n * 200704 + (size_t)(ctaN * 128 + col) * 784 + rem] =
                sy[col * 132 + q];
        }
    }
}

// ---------------------------------------------------------------- launch
extern "C" void kernel_launch(void* const* d_in, const int* in_sizes, int n_in,
                              void* d_out, int out_size) {
    const float* x       = (const float*)d_in[0];
    const float* w_yat   = (const float*)d_in[1];
    const float* alpha   = (const float*)d_in[2];
    const float* w_lin   = (const float*)d_in[3];
    const float* w_short = (const float*)d_in[4];
    float* out = (float*)d_out;

    cudaFuncSetAttribute(gemm_kernel, cudaFuncAttributeMaxDynamicSharedMemorySize, DYN_SMEM);

    // order keeps ncu capture slot on gemm0
    prep_x  <<<dim3(56, 32), 256>>>(x);
    prep_w  <<<512, 256>>>(w_yat, w_lin, w_short);
    prep_psq<<<dim3(28, 32), 28>>>();

    dim3 grid(196, 2);
    gemm_kernel<<<grid, 256, DYN_SMEM>>>(0, alpha, out);   // YAT -> g_yhi
    gemm_kernel<<<grid, 256, DYN_SMEM>>>(1, alpha, out);   // lin + shortcut -> out
}